// round 9
// baseline (speedup 1.0000x reference)
#include <cuda_runtime.h>

#define Bn 64
#define Dd 32
#define Hh 48
#define Ww 48
#define NA (Dd*Hh*Ww)        /* 73728 anchors per batch */
#define TOPK 60
#define NMS_TOPK 20
#define THRESH 0.15f
#define NMS_T 0.05f
#define NBINS 4096
#define NT 1024
#define HF4 (NA/4/2)         /* 9216 float4 per half */
#define F4T (HF4/NT)         /* 9 per thread */
#define CAND_FB 2304
#define PSLOT 320            /* partner staging capacity (mean ~69, 20+ sigma) */
#define T_RAW 2.9f

__device__ unsigned long long g_pc[Bn][PSLOT];
__device__ int g_pcnt[Bn];
__device__ unsigned g_parr[Bn];   /* partner arrivals (monotonic) */
__device__ unsigned g_sarr[Bn];   /* selector arrivals (monotonic) */
__device__ unsigned g_flag[Bn];   /* partner publishes epoch+1 */

__device__ __forceinline__ unsigned fkey(float f) {
    unsigned u = __float_as_uint(f);
    return u ^ ((u & 0x80000000u) ? 0xFFFFFFFFu : 0x80000000u);
}
__device__ __forceinline__ float finv(unsigned k) {
    unsigned u = (k & 0x80000000u) ? (k ^ 0x80000000u) : ~k;
    return __uint_as_float(u);
}
__device__ __forceinline__ void fence_gpu() {
    asm volatile("fence.acq_rel.gpu;" ::: "memory");
}

template<int C>
__device__ __forceinline__ void scan_chunk(const float4* __restrict__ c4,
                                           int f4base, int tid,
                                           int* s_cnt, unsigned long long* cand)
{
    float4 q[C];
    #pragma unroll
    for (int j = 0; j < C; j++) q[j] = c4[f4base + j * NT + tid];
    unsigned hm = 0;
    #pragma unroll
    for (int j = 0; j < C; j++) {
        float mx = fmaxf(fmaxf(q[j].x, q[j].y), fmaxf(q[j].z, q[j].w));
        hm |= (mx > T_RAW) ? (1u << j) : 0u;
    }
    if (hm) {
        #pragma unroll
        for (int j = 0; j < C; j++) {
            if (hm & (1u << j)) {
                int gi = f4base + j * NT + tid;
                #pragma unroll
                for (int k = 0; k < 4; k++) {
                    float f = (k == 0) ? q[j].x : (k == 1) ? q[j].y
                            : (k == 2) ? q[j].z : q[j].w;
                    if (f > T_RAW) {
                        int off = atomicAdd(s_cnt, 1);
                        if (off < CAND_FB) {
                            unsigned idx = (unsigned)(gi * 4 + k);
                            cand[off] =
                                ((unsigned long long)fkey(f) << 32) | (unsigned)(~idx);
                        }
                    }
                }
            }
        }
    }
}

__global__ __launch_bounds__(NT, 1)
void detsplit(const float* __restrict__ Cls,
              const float* __restrict__ Shp,
              const float* __restrict__ Off,
              float* __restrict__ out)
{
    const int role = blockIdx.x;   // 0 = selector (first half), 1 = partner (second half)
    const int b    = blockIdx.y;
    const int tid  = threadIdx.x;

    __shared__ int s_cnt;
    __shared__ union UU {
        unsigned hist[NBINS];                 /* 16 KB, fallback only */
        unsigned long long cand[CAND_FB];     /* 18.4 KB */
    } u;
    __shared__ int partial[NT];
    __shared__ int thr_bin;
    __shared__ int cand_cnt;
    __shared__ int s_pc;
    __shared__ float s_score[TOPK];
    __shared__ float s_ctr[TOPK][3];
    __shared__ float s_ext[TOPK][3];
    __shared__ unsigned char s_valid[TOPK];
    __shared__ unsigned long long s_mask[TOPK];
    __shared__ unsigned long long s_keep;

    const float4* c4 = (const float4*)(Cls + (size_t)b * NA);
    float* ob = out + (size_t)b * TOPK * 8;

    if (tid == 0) s_cnt = 0;
    if (tid < TOPK) s_mask[tid] = 0ull;
    __syncthreads();

    const int hbase = role * HF4;   // this CTA's half, in float4 units

    // ---- scan own half: 9 f4/thread in chunks of 5+4 (MLP 5/4) ----
    scan_chunk<5>(c4, hbase + 0 * NT,      tid, &s_cnt, u.cand);
    scan_chunk<4>(c4, hbase + 5 * NT * 1,  tid, &s_cnt, u.cand);  /* offset 5*NT */
    __syncthreads();

    if (role == 1) {
        // ================= PARTNER: stage to global, fill -1, publish ==========
        int cnt = s_cnt;
        if (tid == 0) g_pcnt[b] = cnt;                   // raw count (overflow detect)
        int w = min(cnt, PSLOT);
        for (int i = tid; i < w; i += NT) g_pc[b][i] = u.cand[i];
        if (tid < TOPK * 8) ob[tid] = -1.0f;             // prefill output
        __syncthreads();                                 // all stores issued
        if (tid == 0) {
            fence_gpu();                                 // release
            unsigned ep = atomicAdd(&g_parr[b], 1u);
            atomicExch(&g_flag[b], ep + 1u);             // publish epoch
        }
        return;
    }

    // ================= SELECTOR: wait for partner, merge, select ===============
    if (tid == 0) {
        unsigned es = atomicAdd(&g_sarr[b], 1u);
        unsigned target = es + 1u;
        volatile unsigned* vf = &g_flag[b];
        while (*vf < target) { }                         // co-resident: single wave
        fence_gpu();                                     // acquire partner's writes
        s_pc = g_pcnt[b];
    }
    __syncthreads();

    const int myc = s_cnt;
    const int pc  = s_pc;
    {
        int w = min(pc, PSLOT);
        int basec = min(myc, CAND_FB);
        for (int i = tid; i < w; i += NT)
            if (basec + i < CAND_FB) u.cand[basec + i] = g_pc[b][i];
    }
    __syncthreads();

    int c = myc + min(pc, PSLOT);
    const bool fast = (pc <= PSLOT) && (c >= TOPK) && (c <= NT) && (myc + pc <= CAND_FB);

    if (fast) {
        // ---------- FAST PATH: rank-select top-60, gather boxes ----------
        bool act = (tid < c);
        unsigned long long k0 = act ? u.cand[tid] : 0ull;

        // scattered box loads issued NOW; overlap with rank loop
        float az = 0, ay = 0, ax = 0;
        float o0 = 0, o1 = 0, o2 = 0, h0 = 0, h1 = 0, h2 = 0;
        if (act) {
            unsigned idx = ~(unsigned)(k0 & 0xFFFFFFFFull);
            int z = (int)idx / (Hh * Ww);
            int rem = (int)idx % (Hh * Ww);
            az = (float)z; ay = (float)(rem / Ww); ax = (float)(rem % Ww);
            size_t base3 = (size_t)b * 3 * NA + idx;
            o0 = Off[base3]; o1 = Off[base3 + NA]; o2 = Off[base3 + 2 * NA];
            h0 = Shp[base3]; h1 = Shp[base3 + NA]; h2 = Shp[base3 + 2 * NA];
        }

        int r0 = 0;
        for (int j = 0; j < c; j++)                      // broadcast LDS
            r0 += (u.cand[j] > k0) ? 1 : 0;

        if (act && r0 < TOPK) {
            float raw = finv((unsigned)(k0 >> 32));
            float sc  = 1.0f / (1.0f + __expf(-raw));
            s_score[r0] = sc;
            s_valid[r0] = (sc > THRESH) ? 1 : 0;
            s_ctr[r0][0] = (az + o0) * 2.0f;             // stride = (2,2,2)
            s_ctr[r0][1] = (ay + o1) * 2.0f;
            s_ctr[r0][2] = (ax + o2) * 2.0f;
            s_ext[r0][0] = 2.0f * h0;
            s_ext[r0][1] = 2.0f * h1;
            s_ext[r0][2] = 2.0f * h2;
        }
        __syncthreads();
    } else {
        // -------- exact histogram fallback over the WHOLE batch (never hit) ------
        const int lane = tid & 31;
        for (int i = tid; i < NBINS; i += NT) u.hist[i] = 0u;
        if (tid == 0) { thr_bin = 0; cand_cnt = 0; }
        __syncthreads();
        for (int i = tid; i < NA / 4; i += NT) {
            float4 v = c4[i];
            #pragma unroll
            for (int k = 0; k < 4; k++) {
                float f = (k == 0) ? v.x : (k == 1) ? v.y : (k == 2) ? v.z : v.w;
                int bin = (int)(fkey(f) >> 20);
                unsigned m = __match_any_sync(0xFFFFFFFFu, bin);
                if (lane == (__ffs(m) - 1))
                    atomicAdd(&u.hist[bin], (unsigned)__popc(m));
            }
        }
        __syncthreads();
        const int BPT = NBINS / NT;                      // 4
        int hb = tid * BPT;
        int loc = 0;
        #pragma unroll
        for (int j = 0; j < BPT; j++) loc += (int)u.hist[hb + j];
        partial[tid] = loc;
        __syncthreads();
        if (tid == 0) {
            int run = 0;
            for (int t = NT - 1; t >= 0; t--) { int p = partial[t]; partial[t] = run; run += p; }
        }
        __syncthreads();
        {
            int cum_above = partial[tid];
            if (cum_above < TOPK && cum_above + loc >= TOPK) {
                int cum = cum_above;
                for (int j = BPT - 1; j >= 0; j--) {
                    cum += (int)u.hist[hb + j];
                    if (cum >= TOPK) { thr_bin = hb + j; break; }
                }
            }
        }
        __syncthreads();
        const unsigned klow = (unsigned)thr_bin << 20;
        __syncthreads();                                 // done with hist before reuse
        for (int i = tid; i < NA / 4; i += NT) {
            float4 v = c4[i];
            #pragma unroll
            for (int k = 0; k < 4; k++) {
                float f = (k == 0) ? v.x : (k == 1) ? v.y : (k == 2) ? v.z : v.w;
                unsigned key = fkey(f);
                if (key >= klow) {
                    int pos = atomicAdd(&cand_cnt, 1);
                    if (pos < CAND_FB) {
                        unsigned idx = (unsigned)(i * 4 + k);
                        u.cand[pos] = ((unsigned long long)key << 32) | (unsigned)(~idx);
                    }
                }
            }
        }
        __syncthreads();

        const int cf = min(cand_cnt, CAND_FB);
        for (int i = tid; i < cf; i += NT) {
            unsigned long long ki = u.cand[i];
            int rank = 0;
            for (int j = 0; j < cf; j++) rank += (u.cand[j] > ki) ? 1 : 0;
            if (rank < TOPK) {
                unsigned key = (unsigned)(ki >> 32);
                unsigned idx = ~(unsigned)(ki & 0xFFFFFFFFull);
                float raw = finv(key);
                float sc  = 1.0f / (1.0f + expf(-raw));
                s_score[rank] = sc;
                s_valid[rank] = (sc > THRESH) ? 1 : 0;
                int z   = (int)idx / (Hh * Ww);
                int rem = (int)idx % (Hh * Ww);
                int y   = rem / Ww;
                int x   = rem % Ww;
                size_t base3 = (size_t)b * 3 * NA + idx;
                float o0 = Off[base3], o1 = Off[base3 + NA], o2 = Off[base3 + 2 * NA];
                float h0 = Shp[base3], h1 = Shp[base3 + NA], h2 = Shp[base3 + 2 * NA];
                s_ctr[rank][0] = ((float)z + o0) * 2.0f;
                s_ctr[rank][1] = ((float)y + o1) * 2.0f;
                s_ctr[rank][2] = ((float)x + o2) * 2.0f;
                s_ext[rank][0] = 2.0f * h0;
                s_ext[rank][1] = 2.0f * h1;
                s_ext[rank][2] = 2.0f * h2;
            }
        }
        __syncthreads();
    }

    // ---- IoU > NMS_T bitmask: 17 strips x 4 cols per row ----
    {
        int i = tid % TOPK;           // row
        int q = tid / TOPK;           // strip (tid < 1020 -> q < 17)
        if (q < 17) {
            float ci0 = s_ctr[i][0], ci1 = s_ctr[i][1], ci2 = s_ctr[i][2];
            float ei0 = s_ext[i][0], ei1 = s_ext[i][1], ei2 = s_ext[i][2];
            float li0 = ci0 - 0.5f * ei0, li1 = ci1 - 0.5f * ei1, li2 = ci2 - 0.5f * ei2;
            float hi0 = ci0 + 0.5f * ei0, hi1 = ci1 + 0.5f * ei1, hi2 = ci2 + 0.5f * ei2;
            float vi  = ei0 * ei1 * ei2;
            unsigned long long m = 0ull;
            int j0 = q * 4;
            #pragma unroll
            for (int t = 0; t < 4; t++) {
                int j = j0 + t;
                if (j < TOPK) {
                    float ej0 = s_ext[j][0], ej1 = s_ext[j][1], ej2 = s_ext[j][2];
                    float lj0 = s_ctr[j][0] - 0.5f * ej0;
                    float lj1 = s_ctr[j][1] - 0.5f * ej1;
                    float lj2 = s_ctr[j][2] - 0.5f * ej2;
                    float hj0 = s_ctr[j][0] + 0.5f * ej0;
                    float hj1 = s_ctr[j][1] + 0.5f * ej1;
                    float hj2 = s_ctr[j][2] + 0.5f * ej2;
                    float d0 = fminf(hi0, hj0) - fmaxf(li0, lj0);
                    float d1 = fminf(hi1, hj1) - fmaxf(li1, lj1);
                    float d2 = fminf(hi2, hj2) - fmaxf(li2, lj2);
                    float inter = fmaxf(d0, 0.0f) * fmaxf(d1, 0.0f) * fmaxf(d2, 0.0f);
                    float vj  = ej0 * ej1 * ej2;
                    float un  = vi + vj - inter;
                    float iou = inter / fmaxf(un, 1e-8f);
                    if (iou > NMS_T) m |= (1ull << j);
                }
            }
            if (m) atomicOr(&s_mask[i], m);
        }
    }
    __syncthreads();

    // ---- greedy NMS on a u64 mask ----
    if (tid == 0) {
        unsigned long long km = 0ull;
        #pragma unroll 4
        for (int i = 0; i < TOPK; i++)
            if (s_valid[i] && !(s_mask[i] & km)) km |= (1ull << i);
        s_keep = km;
    }
    __syncthreads();

    // ---- write kept rows at their rank (partner already -1-filled) ----
    if (tid < TOPK) {
        unsigned long long km = s_keep;
        if ((km >> tid) & 1ull) {
            int rank = __popcll(km & ((1ull << tid) - 1ull));
            if (rank < NMS_TOPK) {
                float* row = ob + (size_t)rank * 8;
                row[0] = 1.0f;
                row[1] = s_score[tid];
                row[2] = s_ctr[tid][0];
                row[3] = s_ctr[tid][1];
                row[4] = s_ctr[tid][2];
                row[5] = s_ext[tid][0];
                row[6] = s_ext[tid][1];
                row[7] = s_ext[tid][2];
            }
        }
    }
}

extern "C" void kernel_launch(void* const* d_in, const int* in_sizes, int n_in,
                              void* d_out, int out_size)
{
    const float* Cls = (const float*)d_in[0];
    const float* Shp = (const float*)d_in[1];
    const float* Off = (const float*)d_in[2];
    float* out = (float*)d_out;

    dim3 grid(2, Bn);        // 128 CTAs <= 148 SMs: single wave, spin-safe
    detsplit<<<grid, NT>>>(Cls, Shp, Off, out);
}

// round 10
// speedup vs baseline: 1.2231x; 1.2231x over previous
#include <cuda_runtime.h>

#define Bn 64
#define Dd 32
#define Hh 48
#define Ww 48
#define NA (Dd*Hh*Ww)        /* 73728 anchors per batch */
#define TOPK 60
#define NMS_TOPK 20
#define THRESH 0.15f
#define NMS_T 0.05f
#define NBINS 4096
#define NT 1024
#define F4T (NA/4/NT)        /* 18 float4 per thread */
#define CHUNK 9              /* 2 rounds x 9 float4, MLP=9 */
#define CAND_FB 2304
#define T_RAW 2.9f

__device__ __forceinline__ unsigned fkey(float f) {
    unsigned u = __float_as_uint(f);
    return u ^ ((u & 0x80000000u) ? 0xFFFFFFFFu : 0x80000000u);
}
__device__ __forceinline__ float finv(unsigned k) {
    unsigned u = (k & 0x80000000u) ? (k ^ 0x80000000u) : ~k;
    return __uint_as_float(u);
}

__global__ __launch_bounds__(NT, 1)
void detone(const float* __restrict__ Cls,
            const float* __restrict__ Shp,
            const float* __restrict__ Off,
            float* __restrict__ out)
{
    const int b   = blockIdx.x;
    const int tid = threadIdx.x;

    __shared__ int s_cnt;
    __shared__ union UU {
        unsigned hist[NBINS];                 /* 16 KB, fallback only */
        unsigned long long cand[CAND_FB];     /* 18.4 KB */
    } u;
    __shared__ int partial[NT];
    __shared__ int thr_bin;
    __shared__ int cand_cnt;
    __shared__ float s_score[TOPK];
    __shared__ float s_ctr[TOPK][3];
    __shared__ float s_ext[TOPK][3];
    __shared__ unsigned char s_valid[TOPK];
    __shared__ unsigned long long s_mask[TOPK];
    __shared__ unsigned long long s_keep;

    const float4* c4 = (const float4*)(Cls + (size_t)b * NA);
    float* ob = out + (size_t)b * TOPK * 8;

    if (tid == 0) s_cnt = 0;
    if (tid < TOPK) s_mask[tid] = 0ull;
    __syncthreads();

    // ================= phase 1: one branchless pass, compact into smem ===========
    #pragma unroll
    for (int ch = 0; ch < F4T / CHUNK; ch++) {           // 2 rounds
        float4 q[CHUNK];
        const int cb = ch * CHUNK;
        #pragma unroll
        for (int j = 0; j < CHUNK; j++) q[j] = c4[(cb + j) * NT + tid];

        unsigned hm = 0;
        #pragma unroll
        for (int j = 0; j < CHUNK; j++) {
            float mx = fmaxf(fmaxf(q[j].x, q[j].y), fmaxf(q[j].z, q[j].w));
            hm |= (mx > T_RAW) ? (1u << j) : 0u;
        }
        if (hm) {                                        // rare
            #pragma unroll
            for (int j = 0; j < CHUNK; j++) {
                if (hm & (1u << j)) {
                    int gi = (cb + j) * NT + tid;
                    #pragma unroll
                    for (int k = 0; k < 4; k++) {
                        float f = (k == 0) ? q[j].x : (k == 1) ? q[j].y
                                : (k == 2) ? q[j].z : q[j].w;
                        if (f > T_RAW) {
                            int off = atomicAdd(&s_cnt, 1);
                            if (off < CAND_FB) {
                                unsigned idx = (unsigned)(gi * 4 + k);
                                u.cand[off] =
                                    ((unsigned long long)fkey(f) << 32) | (unsigned)(~idx);
                            }
                        }
                    }
                }
            }
        }
    }
    // prefill output with -1 (after scan loads issued; overwritten at the end)
    if (tid < TOPK * 8) ob[tid] = -1.0f;
    __syncthreads();

    int c = s_cnt;
    const bool fast = (c >= TOPK) && (c <= NT) && (c <= CAND_FB);

    if (fast) {
        // ---------- FAST PATH: rank-select top-60, gather boxes ----------
        if (tid < c) {                                   // only active warps pay
            unsigned long long k0 = u.cand[tid];

            // scattered box loads issued NOW; overlap with the rank loop
            unsigned idx = ~(unsigned)(k0 & 0xFFFFFFFFull);
            int z = (int)idx / (Hh * Ww);
            int rem = (int)idx % (Hh * Ww);
            float az = (float)z, ay = (float)(rem / Ww), ax = (float)(rem % Ww);
            size_t base3 = (size_t)b * 3 * NA + idx;
            float o0 = Off[base3], o1 = Off[base3 + NA], o2 = Off[base3 + 2 * NA];
            float h0 = Shp[base3], h1 = Shp[base3 + NA], h2 = Shp[base3 + 2 * NA];

            int r0 = 0;
            #pragma unroll 4
            for (int j = 0; j < c; j++)                  // broadcast LDS
                r0 += (u.cand[j] > k0) ? 1 : 0;

            if (r0 < TOPK) {
                float raw = finv((unsigned)(k0 >> 32));
                float sc  = 1.0f / (1.0f + __expf(-raw));
                s_score[r0] = sc;
                s_valid[r0] = (sc > THRESH) ? 1 : 0;
                s_ctr[r0][0] = (az + o0) * 2.0f;         // stride = (2,2,2)
                s_ctr[r0][1] = (ay + o1) * 2.0f;
                s_ctr[r0][2] = (ax + o2) * 2.0f;
                s_ext[r0][0] = 2.0f * h0;
                s_ext[r0][1] = 2.0f * h1;
                s_ext[r0][2] = 2.0f * h2;
            }
        }
        __syncthreads();
    } else {
        // -------- exact histogram fallback (never hit on this data) --------
        const int lane = tid & 31;
        for (int i = tid; i < NBINS; i += NT) u.hist[i] = 0u;
        if (tid == 0) { thr_bin = 0; cand_cnt = 0; }
        __syncthreads();
        for (int i = tid; i < NA / 4; i += NT) {
            float4 v = c4[i];
            #pragma unroll
            for (int k = 0; k < 4; k++) {
                float f = (k == 0) ? v.x : (k == 1) ? v.y : (k == 2) ? v.z : v.w;
                int bin = (int)(fkey(f) >> 20);
                unsigned m = __match_any_sync(0xFFFFFFFFu, bin);
                if (lane == (__ffs(m) - 1))
                    atomicAdd(&u.hist[bin], (unsigned)__popc(m));
            }
        }
        __syncthreads();
        const int BPT = NBINS / NT;                      // 4
        int hbase = tid * BPT;
        int loc = 0;
        #pragma unroll
        for (int j = 0; j < BPT; j++) loc += (int)u.hist[hbase + j];
        partial[tid] = loc;
        __syncthreads();
        if (tid == 0) {
            int run = 0;
            for (int t = NT - 1; t >= 0; t--) { int p = partial[t]; partial[t] = run; run += p; }
        }
        __syncthreads();
        {
            int cum_above = partial[tid];
            if (cum_above < TOPK && cum_above + loc >= TOPK) {
                int cum = cum_above;
                for (int j = BPT - 1; j >= 0; j--) {
                    cum += (int)u.hist[hbase + j];
                    if (cum >= TOPK) { thr_bin = hbase + j; break; }
                }
            }
        }
        __syncthreads();
        const unsigned klow = (unsigned)thr_bin << 20;
        __syncthreads();                                 // done with hist before reuse
        for (int i = tid; i < NA / 4; i += NT) {
            float4 v = c4[i];
            #pragma unroll
            for (int k = 0; k < 4; k++) {
                float f = (k == 0) ? v.x : (k == 1) ? v.y : (k == 2) ? v.z : v.w;
                unsigned key = fkey(f);
                if (key >= klow) {
                    int pos = atomicAdd(&cand_cnt, 1);
                    if (pos < CAND_FB) {
                        unsigned idx = (unsigned)(i * 4 + k);
                        u.cand[pos] = ((unsigned long long)key << 32) | (unsigned)(~idx);
                    }
                }
            }
        }
        __syncthreads();

        const int cf = min(cand_cnt, CAND_FB);
        for (int i = tid; i < cf; i += NT) {
            unsigned long long ki = u.cand[i];
            int rank = 0;
            for (int j = 0; j < cf; j++) rank += (u.cand[j] > ki) ? 1 : 0;
            if (rank < TOPK) {
                unsigned key = (unsigned)(ki >> 32);
                unsigned idx = ~(unsigned)(ki & 0xFFFFFFFFull);
                float raw = finv(key);
                float sc  = 1.0f / (1.0f + expf(-raw));
                s_score[rank] = sc;
                s_valid[rank] = (sc > THRESH) ? 1 : 0;
                int z   = (int)idx / (Hh * Ww);
                int rem = (int)idx % (Hh * Ww);
                int y   = rem / Ww;
                int x   = rem % Ww;
                size_t base3 = (size_t)b * 3 * NA + idx;
                float o0 = Off[base3], o1 = Off[base3 + NA], o2 = Off[base3 + 2 * NA];
                float h0 = Shp[base3], h1 = Shp[base3 + NA], h2 = Shp[base3 + 2 * NA];
                s_ctr[rank][0] = ((float)z + o0) * 2.0f;
                s_ctr[rank][1] = ((float)y + o1) * 2.0f;
                s_ctr[rank][2] = ((float)x + o2) * 2.0f;
                s_ext[rank][0] = 2.0f * h0;
                s_ext[rank][1] = 2.0f * h1;
                s_ext[rank][2] = 2.0f * h2;
            }
        }
        __syncthreads();
    }

    // ---- IoU > NMS_T bitmask: 17 strips x 4 cols per row ----
    {
        int i = tid % TOPK;           // row
        int q = tid / TOPK;           // strip (tid < 1020 -> q < 17)
        if (q < 17) {
            float ci0 = s_ctr[i][0], ci1 = s_ctr[i][1], ci2 = s_ctr[i][2];
            float ei0 = s_ext[i][0], ei1 = s_ext[i][1], ei2 = s_ext[i][2];
            float li0 = ci0 - 0.5f * ei0, li1 = ci1 - 0.5f * ei1, li2 = ci2 - 0.5f * ei2;
            float hi0 = ci0 + 0.5f * ei0, hi1 = ci1 + 0.5f * ei1, hi2 = ci2 + 0.5f * ei2;
            float vi  = ei0 * ei1 * ei2;
            unsigned long long m = 0ull;
            int j0 = q * 4;
            #pragma unroll
            for (int t = 0; t < 4; t++) {
                int j = j0 + t;
                if (j < TOPK) {
                    float ej0 = s_ext[j][0], ej1 = s_ext[j][1], ej2 = s_ext[j][2];
                    float lj0 = s_ctr[j][0] - 0.5f * ej0;
                    float lj1 = s_ctr[j][1] - 0.5f * ej1;
                    float lj2 = s_ctr[j][2] - 0.5f * ej2;
                    float hj0 = s_ctr[j][0] + 0.5f * ej0;
                    float hj1 = s_ctr[j][1] + 0.5f * ej1;
                    float hj2 = s_ctr[j][2] + 0.5f * ej2;
                    float d0 = fminf(hi0, hj0) - fmaxf(li0, lj0);
                    float d1 = fminf(hi1, hj1) - fmaxf(li1, lj1);
                    float d2 = fminf(hi2, hj2) - fmaxf(li2, lj2);
                    float inter = fmaxf(d0, 0.0f) * fmaxf(d1, 0.0f) * fmaxf(d2, 0.0f);
                    float vj  = ej0 * ej1 * ej2;
                    float un  = vi + vj - inter;
                    float iou = inter / fmaxf(un, 1e-8f);
                    if (iou > NMS_T) m |= (1ull << j);
                }
            }
            if (m) atomicOr(&s_mask[i], m);
        }
    }
    __syncthreads();

    // ---- greedy NMS on a u64 mask ----
    if (tid == 0) {
        unsigned long long km = 0ull;
        #pragma unroll 4
        for (int i = 0; i < TOPK; i++)
            if (s_valid[i] && !(s_mask[i] & km)) km |= (1ull << i);
        s_keep = km;
    }
    __syncthreads();

    // ---- write kept rows at their rank (output already -1-filled) ----
    if (tid < TOPK) {
        unsigned long long km = s_keep;
        if ((km >> tid) & 1ull) {
            int rank = __popcll(km & ((1ull << tid) - 1ull));
            if (rank < NMS_TOPK) {
                float* row = ob + (size_t)rank * 8;
                row[0] = 1.0f;
                row[1] = s_score[tid];
                row[2] = s_ctr[tid][0];
                row[3] = s_ctr[tid][1];
                row[4] = s_ctr[tid][2];
                row[5] = s_ext[tid][0];
                row[6] = s_ext[tid][1];
                row[7] = s_ext[tid][2];
            }
        }
    }
}

extern "C" void kernel_launch(void* const* d_in, const int* in_sizes, int n_in,
                              void* d_out, int out_size)
{
    const float* Cls = (const float*)d_in[0];
    const float* Shp = (const float*)d_in[1];
    const float* Off = (const float*)d_in[2];
    float* out = (float*)d_out;

    detone<<<Bn, NT>>>(Cls, Shp, Off, out);
}